// round 4
// baseline (speedup 1.0000x reference)
#include <cuda_runtime.h>
#include <cstdint>

#define NN   8192
#define IND  128
#define OUTD 64
#define NSPLIT 16
#define JCHUNK (NN / NSPLIT)   // 512 j-columns per split
#define JT 32                  // j tile
#define ITILE 128              // i rows per block

// static device scratch (no allocations allowed)
__device__ float g_Wh[(size_t)NN * OUTD];
__device__ float g_s1[NN];
__device__ float g_s2[NN];
__device__ float g_part[(size_t)NSPLIT * NN * OUTD];
__device__ float g_lp[(size_t)NSPLIT * NN];

__device__ __forceinline__ void ffma2(unsigned long long& d, unsigned long long a, unsigned long long b) {
    asm("fma.rn.f32x2 %0, %1, %2, %0;" : "+l"(d) : "l"(a), "l"(b));
}
__device__ __forceinline__ float2 upk2(unsigned long long v) {
    float2 r;
    asm("mov.b64 {%0, %1}, %2;" : "=f"(r.x), "=f"(r.y) : "l"(v));
    return r;
}
// store {v,v} to shared with a single STS.64, no packing movs
__device__ __forceinline__ void sts_dup(void* p, float v) {
    unsigned a = (unsigned)__cvta_generic_to_shared(p);
    asm volatile("st.shared.v2.f32 [%0], {%1, %1};" :: "r"(a), "f"(v) : "memory");
}

// ---------------------------------------------------------------------------
// K1: Wh = x @ W;  s1 = Wh @ a[:64];  s2 = Wh @ a[64:]
// ---------------------------------------------------------------------------
__global__ __launch_bounds__(128) void k1_proj(const float* __restrict__ x,
                                               const float* __restrict__ W,
                                               const float* __restrict__ a) {
    __shared__ float W_sm[IND][OUTD];
    __shared__ float x_sm[32][33];

    const int t  = threadIdx.x;
    const int i0 = blockIdx.x * 32;
    const int dl = t & 15;
    const int rl = t >> 4;

    {
        const float4* src = (const float4*)W;
        float4* dst = (float4*)&W_sm[0][0];
#pragma unroll
        for (int q = 0; q < 16; ++q) dst[t + 128 * q] = src[t + 128 * q];
    }

    float acc[4][4];
#pragma unroll
    for (int rr = 0; rr < 4; ++rr)
#pragma unroll
        for (int dd = 0; dd < 4; ++dd) acc[rr][dd] = 0.f;

    for (int k0 = 0; k0 < IND; k0 += 32) {
        __syncthreads();
#pragma unroll
        for (int q = 0; q < 8; ++q) {
            int idx = t + 128 * q;
            int r = idx >> 5, kk = idx & 31;
            x_sm[r][kk] = x[(size_t)(i0 + r) * IND + k0 + kk];
        }
        __syncthreads();
#pragma unroll
        for (int kk = 0; kk < 32; ++kk) {
            float4 w = *(const float4*)&W_sm[k0 + kk][dl * 4];
#pragma unroll
            for (int rr = 0; rr < 4; ++rr) {
                float xv = x_sm[rl * 4 + rr][kk];
                acc[rr][0] += xv * w.x;
                acc[rr][1] += xv * w.y;
                acc[rr][2] += xv * w.z;
                acc[rr][3] += xv * w.w;
            }
        }
    }

    const float* a1 = a;
    const float* a2 = a + OUTD;
#pragma unroll
    for (int rr = 0; rr < 4; ++rr) {
        int row = i0 + rl * 4 + rr;
        *(float4*)&g_Wh[(size_t)row * OUTD + dl * 4] =
            make_float4(acc[rr][0], acc[rr][1], acc[rr][2], acc[rr][3]);
        float4 av1 = *(const float4*)&a1[dl * 4];
        float4 av2 = *(const float4*)&a2[dl * 4];
        float v1 = acc[rr][0] * av1.x + acc[rr][1] * av1.y + acc[rr][2] * av1.z + acc[rr][3] * av1.w;
        float v2 = acc[rr][0] * av2.x + acc[rr][1] * av2.y + acc[rr][2] * av2.z + acc[rr][3] * av2.w;
#pragma unroll
        for (int o = 8; o >= 1; o >>= 1) {
            v1 += __shfl_xor_sync(0xffffffffu, v1, o, 16);
            v2 += __shfl_xor_sync(0xffffffffu, v2, o, 16);
        }
        if (dl == 0) { g_s1[row] = v1; g_s2[row] = v2; }
    }
}

// ---------------------------------------------------------------------------
// K2: fused attention, j-split. Block = 128 threads, i-tile 128 rows, j-tile 32.
// Thread FMA tile: 8 rows x 8 dims:
//   cg = t&7  -> dims cg*8 .. cg*8+7
//   rg = t>>3 -> rows rg*8 .. rg*8+7 (consecutive)
// p stored transposed+duplicated: p_t[j][row] = {p,p} (ull). A thread's 8 rows
// are 64 contiguous bytes -> 4 LDS.128 feed FFMA2 operands directly.
// Wh row = 8 dims per thread = 2 LDS.128 with 4-lane broadcast.
// ---------------------------------------------------------------------------
__global__ __launch_bounds__(128, 4) void k2_attn(const int* __restrict__ adj) {
    __shared__ unsigned long long p_t[JT][ITILE + 2];  // [j][row] dup, stride 130 ull
    __shared__ float Wh_sm[JT][OUTD + 4];              // stride 68 floats

    const int t     = threadIdx.x;
    const int i0    = blockIdx.x * ITILE;
    const int split = blockIdx.y;
    const int js    = split * JCHUNK;
    const int cg = t & 7;
    const int rg = t >> 3;

    const float s1v = g_s1[i0 + t];
    const int* adjrow = adj + (size_t)(i0 + t) * NN + js;

    float lacc = 0.f;
    unsigned long long acc[8][4];
#pragma unroll
    for (int rr = 0; rr < 8; ++rr)
#pragma unroll
        for (int q = 0; q < 4; ++q) acc[rr][q] = 0ull;

    for (int tile = 0; tile < JCHUNK / JT; ++tile) {
        const int j0 = tile * JT;
        __syncthreads();   // previous tile fully consumed

        // Wh tile: 32 j x 64 d. Thread t: row t>>2, quarter t&3 (4 float4s).
        {
            const int jr = t >> 2, qc = t & 3;
            const float4* src = (const float4*)(g_Wh + (size_t)(js + j0 + jr) * OUTD + qc * 16);
#pragma unroll
            for (int u = 0; u < 4; ++u) *(float4*)&Wh_sm[jr][qc * 16 + 4 * u] = src[u];
        }
        // p tile: thread t owns row t, 32 j, stored transposed+dup
        {
            const int4*   a4p = (const int4*)(adjrow + j0);
            const float4* s4p = (const float4*)(g_s2 + js + j0);
#pragma unroll
            for (int k = 0; k < 8; ++k) {
                int4   a4 = a4p[k];
                float4 s4 = s4p[k];
                float e, pv;
                e = s1v + s4.x; e = fmaxf(e, 0.2f * e); pv = a4.x ? __expf(e) : 0.f;
                lacc += pv; sts_dup(&p_t[4 * k + 0][t], pv);
                e = s1v + s4.y; e = fmaxf(e, 0.2f * e); pv = a4.y ? __expf(e) : 0.f;
                lacc += pv; sts_dup(&p_t[4 * k + 1][t], pv);
                e = s1v + s4.z; e = fmaxf(e, 0.2f * e); pv = a4.z ? __expf(e) : 0.f;
                lacc += pv; sts_dup(&p_t[4 * k + 2][t], pv);
                e = s1v + s4.w; e = fmaxf(e, 0.2f * e); pv = a4.w ? __expf(e) : 0.f;
                lacc += pv; sts_dup(&p_t[4 * k + 3][t], pv);
            }
        }
        __syncthreads();

        // acc[rr][dims] += p[rg*8+rr][j] * Wh[j][cg*8 + dims]
#pragma unroll 2
        for (int j = 0; j < JT; ++j) {
            const unsigned long long* pr = &p_t[j][rg * 8];
            ulonglong2 p01 = *(const ulonglong2*)(pr + 0);
            ulonglong2 p23 = *(const ulonglong2*)(pr + 2);
            ulonglong2 p45 = *(const ulonglong2*)(pr + 4);
            ulonglong2 p67 = *(const ulonglong2*)(pr + 6);
            ulonglong2 w0 = *(const ulonglong2*)&Wh_sm[j][cg * 8];
            ulonglong2 w1 = *(const ulonglong2*)&Wh_sm[j][cg * 8 + 4];
            ffma2(acc[0][0], w0.x, p01.x); ffma2(acc[0][1], w0.y, p01.x);
            ffma2(acc[0][2], w1.x, p01.x); ffma2(acc[0][3], w1.y, p01.x);
            ffma2(acc[1][0], w0.x, p01.y); ffma2(acc[1][1], w0.y, p01.y);
            ffma2(acc[1][2], w1.x, p01.y); ffma2(acc[1][3], w1.y, p01.y);
            ffma2(acc[2][0], w0.x, p23.x); ffma2(acc[2][1], w0.y, p23.x);
            ffma2(acc[2][2], w1.x, p23.x); ffma2(acc[2][3], w1.y, p23.x);
            ffma2(acc[3][0], w0.x, p23.y); ffma2(acc[3][1], w0.y, p23.y);
            ffma2(acc[3][2], w1.x, p23.y); ffma2(acc[3][3], w1.y, p23.y);
            ffma2(acc[4][0], w0.x, p45.x); ffma2(acc[4][1], w0.y, p45.x);
            ffma2(acc[4][2], w1.x, p45.x); ffma2(acc[4][3], w1.y, p45.x);
            ffma2(acc[5][0], w0.x, p45.y); ffma2(acc[5][1], w0.y, p45.y);
            ffma2(acc[5][2], w1.x, p45.y); ffma2(acc[5][3], w1.y, p45.y);
            ffma2(acc[6][0], w0.x, p67.x); ffma2(acc[6][1], w0.y, p67.x);
            ffma2(acc[6][2], w1.x, p67.x); ffma2(acc[6][3], w1.y, p67.x);
            ffma2(acc[7][0], w0.x, p67.y); ffma2(acc[7][1], w0.y, p67.y);
            ffma2(acc[7][2], w1.x, p67.y); ffma2(acc[7][3], w1.y, p67.y);
        }
    }

    g_lp[(size_t)split * NN + i0 + t] = lacc;

    // store partials: rows rg*8+rr, dims cg*8..+7
#pragma unroll
    for (int rr = 0; rr < 8; ++rr) {
        const int row = i0 + rg * 8 + rr;
        float* dst = &g_part[((size_t)split * NN + row) * OUTD + cg * 8];
        float2 a0 = upk2(acc[rr][0]);
        float2 a1 = upk2(acc[rr][1]);
        float2 a2 = upk2(acc[rr][2]);
        float2 a3 = upk2(acc[rr][3]);
        *(float4*)&dst[0] = make_float4(a0.x, a0.y, a1.x, a1.y);
        *(float4*)&dst[4] = make_float4(a2.x, a2.y, a3.x, a3.y);
    }
}

// ---------------------------------------------------------------------------
// K3: reduce NSPLIT partials, normalize, ELU.
// ---------------------------------------------------------------------------
__global__ __launch_bounds__(128) void k3_reduce(float* __restrict__ out) {
    const int q   = blockIdx.x * 128 + threadIdx.x;
    const int row = q >> 4;
    const int c4  = (q & 15) * 4;

    float l = 0.f;
#pragma unroll
    for (int s = 0; s < NSPLIT; ++s) l += g_lp[(size_t)s * NN + row];
    const float inv = 1.0f / l;

    float4 acc = make_float4(0.f, 0.f, 0.f, 0.f);
#pragma unroll
    for (int s = 0; s < NSPLIT; ++s) {
        float4 v = *(const float4*)&g_part[((size_t)s * NN + row) * OUTD + c4];
        acc.x += v.x; acc.y += v.y; acc.z += v.z; acc.w += v.w;
    }
    acc.x *= inv; acc.y *= inv; acc.z *= inv; acc.w *= inv;
    acc.x = acc.x > 0.f ? acc.x : expm1f(acc.x);
    acc.y = acc.y > 0.f ? acc.y : expm1f(acc.y);
    acc.z = acc.z > 0.f ? acc.z : expm1f(acc.z);
    acc.w = acc.w > 0.f ? acc.w : expm1f(acc.w);
    *(float4*)&out[(size_t)row * OUTD + c4] = acc;
}

extern "C" void kernel_launch(void* const* d_in, const int* in_sizes, int n_in,
                              void* d_out, int out_size) {
    const float* x   = (const float*)d_in[0];
    const int*   adj = (const int*)d_in[1];
    const float* W   = (const float*)d_in[2];
    const float* a   = (const float*)d_in[3];
    float* out = (float*)d_out;

    k1_proj<<<256, 128>>>(x, W, a);
    k2_attn<<<dim3(NN / ITILE, NSPLIT), 128>>>(adj);
    k3_reduce<<<(NN * OUTD / 4) / 128, 128>>>(out);
}

// round 6
// speedup vs baseline: 1.3307x; 1.3307x over previous
#include <cuda_runtime.h>
#include <cuda_bf16.h>
#include <cstdint>

#define NN   8192
#define IND  128
#define OUTD 64
#define NSPLIT 8
#define JCHUNK (NN / NSPLIT)   // 1024 j per split
#define JT 32                  // K tile
#define ITILE 128              // M rows per block

// static device scratch (no allocations allowed)
__device__ float g_s1[NN];
__device__ float g_s2[NN];
__device__ __nv_bfloat16 g_WhT_hi[(size_t)OUTD * NN];  // [d][j]
__device__ __nv_bfloat16 g_WhT_lo[(size_t)OUTD * NN];
__device__ float g_part[(size_t)NSPLIT * NN * OUTD];
__device__ float g_lp[(size_t)NSPLIT * NN];

__device__ __forceinline__ uint32_t smem_u32(const void* p) {
    return (uint32_t)__cvta_generic_to_shared(p);
}
__device__ __forceinline__ void ldsm_x4(uint32_t& r0, uint32_t& r1, uint32_t& r2, uint32_t& r3, uint32_t a) {
    asm volatile("ldmatrix.sync.aligned.m8n8.x4.shared.b16 {%0,%1,%2,%3}, [%4];"
                 : "=r"(r0), "=r"(r1), "=r"(r2), "=r"(r3) : "r"(a));
}
__device__ __forceinline__ void ldsm_x2(uint32_t& r0, uint32_t& r1, uint32_t a) {
    asm volatile("ldmatrix.sync.aligned.m8n8.x2.shared.b16 {%0,%1}, [%2];"
                 : "=r"(r0), "=r"(r1) : "r"(a));
}
__device__ __forceinline__ void mma_bf16(float* c, const uint32_t* A, uint32_t b0, uint32_t b1) {
    asm volatile(
        "mma.sync.aligned.m16n8k16.row.col.f32.bf16.bf16.f32 "
        "{%0,%1,%2,%3}, {%4,%5,%6,%7}, {%8,%9}, {%0,%1,%2,%3};"
        : "+f"(c[0]), "+f"(c[1]), "+f"(c[2]), "+f"(c[3])
        : "r"(A[0]), "r"(A[1]), "r"(A[2]), "r"(A[3]), "r"(b0), "r"(b1));
}

// ---------------------------------------------------------------------------
// K1: Wh = x@W; s1/s2 = Wh@a halves; WhT hi/lo bf16 (transposed)
// ---------------------------------------------------------------------------
__global__ __launch_bounds__(128) void k1_proj(const float* __restrict__ x,
                                               const float* __restrict__ W,
                                               const float* __restrict__ a) {
    __shared__ float W_sm[IND][OUTD];
    __shared__ float x_sm[32][33];

    const int t  = threadIdx.x;
    const int i0 = blockIdx.x * 32;
    const int dl = t & 15;
    const int rl = t >> 4;

    {
        const float4* src = (const float4*)W;
        float4* dst = (float4*)&W_sm[0][0];
#pragma unroll
        for (int q = 0; q < 16; ++q) dst[t + 128 * q] = src[t + 128 * q];
    }

    float acc[4][4];
#pragma unroll
    for (int rr = 0; rr < 4; ++rr)
#pragma unroll
        for (int dd = 0; dd < 4; ++dd) acc[rr][dd] = 0.f;

    for (int k0 = 0; k0 < IND; k0 += 32) {
        __syncthreads();
#pragma unroll
        for (int q = 0; q < 8; ++q) {
            int idx = t + 128 * q;
            int r = idx >> 5, kk = idx & 31;
            x_sm[r][kk] = x[(size_t)(i0 + r) * IND + k0 + kk];
        }
        __syncthreads();
#pragma unroll
        for (int kk = 0; kk < 32; ++kk) {
            float4 w = *(const float4*)&W_sm[k0 + kk][dl * 4];
#pragma unroll
            for (int rr = 0; rr < 4; ++rr) {
                float xv = x_sm[rl * 4 + rr][kk];
                acc[rr][0] += xv * w.x;
                acc[rr][1] += xv * w.y;
                acc[rr][2] += xv * w.z;
                acc[rr][3] += xv * w.w;
            }
        }
    }

    const float* a1 = a;
    const float* a2 = a + OUTD;
#pragma unroll
    for (int rr = 0; rr < 4; ++rr) {
        int row = i0 + rl * 4 + rr;
#pragma unroll
        for (int dd = 0; dd < 4; ++dd) {
            int d = dl * 4 + dd;
            float v = acc[rr][dd];
            __nv_bfloat16 h = __float2bfloat16(v);
            float hf = __bfloat162float(h);
            g_WhT_hi[(size_t)d * NN + row] = h;
            g_WhT_lo[(size_t)d * NN + row] = __float2bfloat16(v - hf);
        }
        float4 av1 = *(const float4*)&a1[dl * 4];
        float4 av2 = *(const float4*)&a2[dl * 4];
        float v1 = acc[rr][0] * av1.x + acc[rr][1] * av1.y + acc[rr][2] * av1.z + acc[rr][3] * av1.w;
        float v2 = acc[rr][0] * av2.x + acc[rr][1] * av2.y + acc[rr][2] * av2.z + acc[rr][3] * av2.w;
#pragma unroll
        for (int o = 8; o >= 1; o >>= 1) {
            v1 += __shfl_xor_sync(0xffffffffu, v1, o, 16);
            v2 += __shfl_xor_sync(0xffffffffu, v2, o, 16);
        }
        if (dl == 0) { g_s1[row] = v1; g_s2[row] = v2; }
    }
}

// ---------------------------------------------------------------------------
// K2: p on CUDA cores (exp), PV on mma.sync bf16 hi/lo (3 terms).
// Block 128 threads / 4 warps; warp w owns rows [w*32, w*32+32).
// A tiles: p_hi/p_lo [128][JT] bf16, row stride 40 (conflict-free ldmatrix).
// B tiles: WhT hi/lo [64][JT] bf16 ([n][k] -> col-major frag via ldmatrix.x2).
// ---------------------------------------------------------------------------
__global__ __launch_bounds__(128) void k2_attn_mma(const int* __restrict__ adj) {
    __shared__ __nv_bfloat16 A_hi[ITILE][JT + 8];
    __shared__ __nv_bfloat16 A_lo[ITILE][JT + 8];
    __shared__ __nv_bfloat16 B_hi[OUTD][JT + 8];
    __shared__ __nv_bfloat16 B_lo[OUTD][JT + 8];

    const int t     = threadIdx.x;
    const int wid   = t >> 5;
    const int lid   = t & 31;
    const int i0    = blockIdx.x * ITILE;
    const int split = blockIdx.y;
    const int js    = split * JCHUNK;

    const float s1v = g_s1[i0 + t];
    const int* adjrow = adj + (size_t)(i0 + t) * NN + js;

    float lacc = 0.f;
    float c[2][8][4];
#pragma unroll
    for (int mt = 0; mt < 2; ++mt)
#pragma unroll
        for (int nt = 0; nt < 8; ++nt)
#pragma unroll
            for (int q = 0; q < 4; ++q) c[mt][nt][q] = 0.f;

    // ldmatrix addresses (constant across tiles)
    const int wb = wid * 32;
    const uint32_t a_base0 = smem_u32(&A_hi[wb + (lid & 15)][(lid >> 4) * 8]);
    const uint32_t a_base1 = smem_u32(&A_lo[wb + (lid & 15)][(lid >> 4) * 8]);
    const int bl = lid & 15;
    const uint32_t b_row = (uint32_t)(bl & 7);
    const uint32_t b_k   = (uint32_t)((bl >> 3) * 8);
    const uint32_t b_base0 = smem_u32(&B_hi[b_row][b_k]);
    const uint32_t b_base1 = smem_u32(&B_lo[b_row][b_k]);
    const uint32_t ROWB = (JT + 8) * 2;   // 80 bytes per row

    for (int tile = 0; tile < JCHUNK / JT; ++tile) {
        const int j0 = tile * JT;
        __syncthreads();   // previous tile's smem fully consumed

        // ---- B tiles: thread t -> n row t>>1, k-half (t&1)*16
        {
            const int n = t >> 1, kofs = (t & 1) * 16;
            const __nv_bfloat16* sh = g_WhT_hi + (size_t)n * NN + js + j0 + kofs;
            const __nv_bfloat16* sl = g_WhT_lo + (size_t)n * NN + js + j0 + kofs;
            *(uint4*)&B_hi[n][kofs]     = *(const uint4*)sh;
            *(uint4*)&B_hi[n][kofs + 8] = *(const uint4*)(sh + 8);
            *(uint4*)&B_lo[n][kofs]     = *(const uint4*)sl;
            *(uint4*)&B_lo[n][kofs + 8] = *(const uint4*)(sl + 8);
        }

        // ---- A tiles: thread t computes p for row t, JT j -> bf16 hi/lo
        const int4*   a4p = (const int4*)(adjrow + j0);
        const float4* s4p = (const float4*)(g_s2 + js + j0);
#pragma unroll
        for (int k = 0; k < JT / 8; ++k) {
            int4   aA = a4p[2 * k], aB = a4p[2 * k + 1];
            float4 sA = s4p[2 * k], sB = s4p[2 * k + 1];
            float p0, p1, p2, p3, p4, p5, p6, p7, e;
            e = s1v + sA.x; e = fmaxf(e, 0.2f * e); p0 = aA.x ? __expf(e) : 0.f;
            e = s1v + sA.y; e = fmaxf(e, 0.2f * e); p1 = aA.y ? __expf(e) : 0.f;
            e = s1v + sA.z; e = fmaxf(e, 0.2f * e); p2 = aA.z ? __expf(e) : 0.f;
            e = s1v + sA.w; e = fmaxf(e, 0.2f * e); p3 = aA.w ? __expf(e) : 0.f;
            e = s1v + sB.x; e = fmaxf(e, 0.2f * e); p4 = aB.x ? __expf(e) : 0.f;
            e = s1v + sB.y; e = fmaxf(e, 0.2f * e); p5 = aB.y ? __expf(e) : 0.f;
            e = s1v + sB.z; e = fmaxf(e, 0.2f * e); p6 = aB.z ? __expf(e) : 0.f;
            e = s1v + sB.w; e = fmaxf(e, 0.2f * e); p7 = aB.w ? __expf(e) : 0.f;
            lacc += ((p0 + p1) + (p2 + p3)) + ((p4 + p5) + (p6 + p7));

            __nv_bfloat162 h01 = __float22bfloat162_rn(make_float2(p0, p1));
            __nv_bfloat162 h23 = __float22bfloat162_rn(make_float2(p2, p3));
            __nv_bfloat162 h45 = __float22bfloat162_rn(make_float2(p4, p5));
            __nv_bfloat162 h67 = __float22bfloat162_rn(make_float2(p6, p7));
            uint32_t u01 = *(uint32_t*)&h01, u23 = *(uint32_t*)&h23;
            uint32_t u45 = *(uint32_t*)&h45, u67 = *(uint32_t*)&h67;
            *(uint4*)&A_hi[t][k * 8] = make_uint4(u01, u23, u45, u67);

            float l0 = p0 - __uint_as_float(u01 << 16);
            float l1 = p1 - __uint_as_float(u01 & 0xffff0000u);
            float l2 = p2 - __uint_as_float(u23 << 16);
            float l3 = p3 - __uint_as_float(u23 & 0xffff0000u);
            float l4 = p4 - __uint_as_float(u45 << 16);
            float l5 = p5 - __uint_as_float(u45 & 0xffff0000u);
            float l6 = p6 - __uint_as_float(u67 << 16);
            float l7 = p7 - __uint_as_float(u67 & 0xffff0000u);
            __nv_bfloat162 q01 = __float22bfloat162_rn(make_float2(l0, l1));
            __nv_bfloat162 q23 = __float22bfloat162_rn(make_float2(l2, l3));
            __nv_bfloat162 q45 = __float22bfloat162_rn(make_float2(l4, l5));
            __nv_bfloat162 q67 = __float22bfloat162_rn(make_float2(l6, l7));
            *(uint4*)&A_lo[t][k * 8] = make_uint4(*(uint32_t*)&q01, *(uint32_t*)&q23,
                                                  *(uint32_t*)&q45, *(uint32_t*)&q67);
        }
        __syncthreads();

        // ---- MMA phase: per warp 32 rows x 64 dims x JT k, 3 terms
#pragma unroll
        for (int kt = 0; kt < JT / 16; ++kt) {
            uint32_t Ah[2][4], Al[2][4];
#pragma unroll
            for (int mt = 0; mt < 2; ++mt) {
                ldsm_x4(Ah[mt][0], Ah[mt][1], Ah[mt][2], Ah[mt][3],
                        a_base0 + (uint32_t)(mt * 16) * ROWB + kt * 32);
                ldsm_x4(Al[mt][0], Al[mt][1], Al[mt][2], Al[mt][3],
                        a_base1 + (uint32_t)(mt * 16) * ROWB + kt * 32);
            }
#pragma unroll
            for (int nt = 0; nt < 8; ++nt) {
                uint32_t bh0, bh1, bl0, bl1;
                ldsm_x2(bh0, bh1, b_base0 + (uint32_t)(nt * 8) * ROWB + kt * 32);
                ldsm_x2(bl0, bl1, b_base1 + (uint32_t)(nt * 8) * ROWB + kt * 32);
#pragma unroll
                for (int mt = 0; mt < 2; ++mt) {
                    mma_bf16(c[mt][nt], Ah[mt], bh0, bh1);
                    mma_bf16(c[mt][nt], Ah[mt], bl0, bl1);
                    mma_bf16(c[mt][nt], Al[mt], bh0, bh1);
                }
            }
        }
    }

    g_lp[(size_t)split * NN + i0 + t] = lacc;

    // ---- epilogue: write raw partials from c fragments
    const int rbase = i0 + wid * 32 + (lid >> 2);
    const int cbase = 2 * (lid & 3);
#pragma unroll
    for (int mt = 0; mt < 2; ++mt) {
#pragma unroll
        for (int nt = 0; nt < 8; ++nt) {
            const int col = nt * 8 + cbase;
            float* d0 = &g_part[((size_t)split * NN + rbase + mt * 16) * OUTD + col];
            float* d1 = &g_part[((size_t)split * NN + rbase + mt * 16 + 8) * OUTD + col];
            *(float2*)d0 = make_float2(c[mt][nt][0], c[mt][nt][1]);
            *(float2*)d1 = make_float2(c[mt][nt][2], c[mt][nt][3]);
        }
    }
}

// ---------------------------------------------------------------------------
// K3: reduce NSPLIT partials, normalize, ELU.
// ---------------------------------------------------------------------------
__global__ __launch_bounds__(128) void k3_reduce(float* __restrict__ out) {
    const int q   = blockIdx.x * 128 + threadIdx.x;
    const int row = q >> 4;
    const int c4  = (q & 15) * 4;

    float l = 0.f;
#pragma unroll
    for (int s = 0; s < NSPLIT; ++s) l += g_lp[(size_t)s * NN + row];
    const float inv = 1.0f / l;

    float4 acc = make_float4(0.f, 0.f, 0.f, 0.f);
#pragma unroll
    for (int s = 0; s < NSPLIT; ++s) {
        float4 v = *(const float4*)&g_part[((size_t)s * NN + row) * OUTD + c4];
        acc.x += v.x; acc.y += v.y; acc.z += v.z; acc.w += v.w;
    }
    acc.x *= inv; acc.y *= inv; acc.z *= inv; acc.w *= inv;
    acc.x = acc.x > 0.f ? acc.x : expm1f(acc.x);
    acc.y = acc.y > 0.f ? acc.y : expm1f(acc.y);
    acc.z = acc.z > 0.f ? acc.z : expm1f(acc.z);
    acc.w = acc.w > 0.f ? acc.w : expm1f(acc.w);
    *(float4*)&out[(size_t)row * OUTD + c4] = acc;
}

extern "C" void kernel_launch(void* const* d_in, const int* in_sizes, int n_in,
                              void* d_out, int out_size) {
    const float* x   = (const float*)d_in[0];
    const int*   adj = (const int*)d_in[1];
    const float* W   = (const float*)d_in[2];
    const float* a   = (const float*)d_in[3];
    float* out = (float*)d_out;

    k1_proj<<<256, 128>>>(x, W, a);
    k2_attn_mma<<<dim3(NN / ITILE, NSPLIT), 128>>>(adj);
    k3_reduce<<<(NN * OUTD / 4) / 128, 128>>>(out);
}